// round 5
// baseline (speedup 1.0000x reference)
#include <cuda_runtime.h>
#include <cuda_fp16.h>
#include <cstdint>

// Problem dims (fixed for this dataset entry)
// x: [B*S=16384, H=1024] fp32 ; conv_w: [L=20, H, H] ; norm_w: [H]
#define HDIM 1024
#define MDIM 16384

// Scratch (allocation-free rule: __device__ globals)
__device__ __align__(256) __half g_Wh[HDIM * HDIM];          // reduced weights fp16, [o][i]
__device__ __align__(256) __half g_xh[(size_t)MDIM * HDIM];  // x in fp16
__device__ __align__(256) __half g_yh[(size_t)MDIM * HDIM];  // GEMM output (pre-norm), fp16

// ---------------------------------------------------------------------------
// Kernel 1 (merged prep):
//   blocks [0, nbW)        : W[o,i] = (sum_l conv_w[l,o,i]) / L -> fp16
//   blocks [nbW, nbW+nbX)  : x fp32 -> fp16
// ---------------------------------------------------------------------------
__global__ __launch_bounds__(256) void prep_kernel(const float4* __restrict__ x,
                                                   const float4* __restrict__ w,
                                                   int L, int HH4, int n4, int nbW,
                                                   float inv_l) {
    const int tid = threadIdx.x;
    if ((int)blockIdx.x < nbW) {
        int idx = blockIdx.x * 256 + tid;
        if (idx >= HH4) return;
        float4 s = make_float4(0.f, 0.f, 0.f, 0.f);
#pragma unroll 4
        for (int l = 0; l < L; ++l) {
            float4 v = w[(size_t)l * HH4 + idx];
            s.x += v.x; s.y += v.y; s.z += v.z; s.w += v.w;
        }
        __half2* out = reinterpret_cast<__half2*>(g_Wh);
        out[2 * idx]     = __floats2half2_rn(s.x * inv_l, s.y * inv_l);
        out[2 * idx + 1] = __floats2half2_rn(s.z * inv_l, s.w * inv_l);
    } else {
        int idx = (blockIdx.x - nbW) * 256 + tid;
        if (idx >= n4) return;
        float4 v = x[idx];
        __half2* out = reinterpret_cast<__half2*>(g_xh);
        out[2 * idx]     = __floats2half2_rn(v.x, v.y);
        out[2 * idx + 1] = __floats2half2_rn(v.z, v.w);
    }
}

// ---------------------------------------------------------------------------
// Kernel 2: GEMM  C[m,n] = sum_k A[m,k]*B[n,k]   (A=g_xh, B=g_Wh, C=g_yh fp16)
// 128x128 CTA tile, BK=64 (128B rows, SW128 swizzle), 3-stage cp.async,
// 8 warps (4x2, warp tile 32x64), fragment double-buffering, mma.m16n8k16.
// ---------------------------------------------------------------------------
#define GBM 128
#define GBN 128
#define BK 64
#define NSTAGE 3
#define STB (128 * 128)               // 16KB per operand-stage
#define SA(s) ((s) * STB)
#define SB(s) (NSTAGE * STB + (s) * STB)
#define GEMM_SMEM_BYTES (2 * NSTAGE * STB)  // 98304

__device__ __forceinline__ uint32_t sw128(uint32_t off) {
    return off ^ ((off >> 3) & 0x70);
}

__device__ __forceinline__ void cp16(uint32_t sp, const void* gp) {
    asm volatile("cp.async.cg.shared.global [%0], [%1], 16;\n" :: "r"(sp), "l"(gp));
}

__device__ __forceinline__ void ldmx4(uint32_t& r0, uint32_t& r1, uint32_t& r2, uint32_t& r3,
                                      uint32_t addr) {
    asm volatile("ldmatrix.sync.aligned.m8n8.x4.shared.b16 {%0,%1,%2,%3}, [%4];"
                 : "=r"(r0), "=r"(r1), "=r"(r2), "=r"(r3) : "r"(addr));
}

__device__ __forceinline__ void mma16816(float* c, const uint32_t* a, const uint32_t* b) {
    asm volatile(
        "mma.sync.aligned.m16n8k16.row.col.f32.f16.f16.f32 "
        "{%0,%1,%2,%3}, {%4,%5,%6,%7}, {%8,%9}, {%0,%1,%2,%3};"
        : "+f"(c[0]), "+f"(c[1]), "+f"(c[2]), "+f"(c[3])
        : "r"(a[0]), "r"(a[1]), "r"(a[2]), "r"(a[3]), "r"(b[0]), "r"(b[1]));
}

// Fill stage s with K-chunk kc (64 halfs = 128B per row).
__device__ __forceinline__ void load_stage(char* smem, int s,
                                           int m0, int n0, int kc, int tid) {
    uint32_t aBase = (uint32_t)__cvta_generic_to_shared(smem + SA(s));
    uint32_t bBase = (uint32_t)__cvta_generic_to_shared(smem + SB(s));
    const char* gA = (const char*)(g_xh + (size_t)m0 * HDIM) + kc * 128;
    const char* gB = (const char*)(g_Wh + (size_t)n0 * HDIM) + kc * 128;
#pragma unroll
    for (int it = 0; it < 4; ++it) {        // A: 128 rows * 8 x 16B = 1024 ops
        int idx = tid + it * 256;
        int row = idx >> 3, i = idx & 7;
        uint32_t off = sw128((uint32_t)(row * 128 + i * 16));
        cp16(aBase + off, gA + (size_t)row * 2048 + i * 16);
    }
#pragma unroll
    for (int it = 0; it < 4; ++it) {        // B: 128 rows * 8 x 16B
        int idx = tid + it * 256;
        int row = idx >> 3, i = idx & 7;
        uint32_t off = sw128((uint32_t)(row * 128 + i * 16));
        cp16(bBase + off, gB + (size_t)row * 2048 + i * 16);
    }
    asm volatile("cp.async.commit_group;\n" ::: "memory");
}

// Load fragments for K-substep kk (0..3) of stage s for this warp.
__device__ __forceinline__ void load_frags(char* smem, int s, int kk,
                                           int wm, int wn, int lane,
                                           uint32_t afr[2][4], uint32_t bfr[8][2]) {
    uint32_t aBase = (uint32_t)__cvta_generic_to_shared(smem + SA(s));
    uint32_t bBase = (uint32_t)__cvta_generic_to_shared(smem + SB(s));
#pragma unroll
    for (int mt = 0; mt < 2; ++mt) {
        int row = wm * 32 + mt * 16 + (lane & 15);
        int colB = kk * 32 + (lane >> 4) * 16;
        uint32_t ad = aBase + sw128((uint32_t)(row * 128 + colB));
        ldmx4(afr[mt][0], afr[mt][1], afr[mt][2], afr[mt][3], ad);
    }
#pragma unroll
    for (int pj = 0; pj < 4; ++pj) {
        int row = wn * 64 + pj * 16 + (lane >> 4) * 8 + (lane & 7);
        int colB = kk * 32 + ((lane >> 3) & 1) * 16;
        uint32_t ad = bBase + sw128((uint32_t)(row * 128 + colB));
        uint32_t r0, r1, r2, r3;
        ldmx4(r0, r1, r2, r3, ad);
        bfr[2 * pj][0] = r0; bfr[2 * pj][1] = r1;
        bfr[2 * pj + 1][0] = r2; bfr[2 * pj + 1][1] = r3;
    }
}

__global__ __launch_bounds__(256) void gemm_kernel() {
    extern __shared__ char smem[];
    const int tid  = threadIdx.x;
    const int lane = tid & 31;
    const int warp = tid >> 5;
    const int wm = warp >> 1;   // 0..3 : 32-row slab
    const int wn = warp & 1;    // 0..1 : 64-col slab
    const int m0 = blockIdx.y * GBM;
    const int n0 = blockIdx.x * GBN;

    float acc[2][8][4];
#pragma unroll
    for (int mt = 0; mt < 2; ++mt)
#pragma unroll
        for (int nt = 0; nt < 8; ++nt)
#pragma unroll
            for (int i = 0; i < 4; ++i) acc[mt][nt][i] = 0.f;

    const int KT = HDIM / BK;  // 16

    load_stage(smem, 0, m0, n0, 0, tid);
    load_stage(smem, 1, m0, n0, 1, tid);
    load_stage(smem, 2, m0, n0, 2, tid);

    uint32_t afr[2][2][4];
    uint32_t bfr[2][8][2];

    for (int kt = 0; kt < KT; ++kt) {
        const int s = kt % NSTAGE;
        asm volatile("cp.async.wait_group %0;\n" :: "n"(2) : "memory");
        __syncthreads();

        load_frags(smem, s, 0, wm, wn, lane, afr[0], bfr[0]);
#pragma unroll
        for (int kk = 0; kk < 4; ++kk) {
            if (kk < 3)
                load_frags(smem, s, kk + 1, wm, wn, lane,
                           afr[(kk + 1) & 1], bfr[(kk + 1) & 1]);
#pragma unroll
            for (int mt = 0; mt < 2; ++mt)
#pragma unroll
                for (int nt = 0; nt < 8; ++nt)
                    mma16816(acc[mt][nt], afr[kk & 1][mt], bfr[kk & 1][nt]);
        }

        __syncthreads();
        if (kt + NSTAGE < KT) load_stage(smem, s, m0, n0, kt + NSTAGE, tid);
    }

    // Epilogue: write fp16 y
#pragma unroll
    for (int mt = 0; mt < 2; ++mt) {
#pragma unroll
        for (int nt = 0; nt < 8; ++nt) {
            int row = m0 + wm * 32 + mt * 16 + (lane >> 2);
            int col = n0 + wn * 64 + nt * 8 + (lane & 3) * 2;
            __half2 h0 = __floats2half2_rn(acc[mt][nt][0], acc[mt][nt][1]);
            __half2 h1 = __floats2half2_rn(acc[mt][nt][2], acc[mt][nt][3]);
            *reinterpret_cast<__half2*>(g_yh + (size_t)row * HDIM + col) = h0;
            *reinterpret_cast<__half2*>(g_yh + (size_t)(row + 8) * HDIM + col) = h1;
        }
    }
}

// ---------------------------------------------------------------------------
// Kernel 3: RMSNorm, one WARP per row (no block barrier), 8 rows per block.
// y fp16 in, out fp32. Each lane holds 32 halfs (8 x uint2).
// ---------------------------------------------------------------------------
__global__ __launch_bounds__(256) void rmsnorm_kernel(const float4* __restrict__ nw,
                                                      float4* __restrict__ out) {
    const int lane = threadIdx.x & 31;
    const int warp = threadIdx.x >> 5;
    const int row  = blockIdx.x * 8 + warp;

    const uint2* yr = reinterpret_cast<const uint2*>(g_yh + (size_t)row * HDIM);

    uint2 u[8];
#pragma unroll
    for (int it = 0; it < 8; ++it) u[it] = yr[it * 32 + lane];

    float s = 0.f;
#pragma unroll
    for (int it = 0; it < 8; ++it) {
        float2 f0 = __half22float2(*reinterpret_cast<__half2*>(&u[it].x));
        float2 f1 = __half22float2(*reinterpret_cast<__half2*>(&u[it].y));
        s += f0.x * f0.x + f0.y * f0.y + f1.x * f1.x + f1.y * f1.y;
    }
#pragma unroll
    for (int o = 16; o > 0; o >>= 1) s += __shfl_xor_sync(0xFFFFFFFFu, s, o);

    const float scale = rsqrtf(s * (1.0f / HDIM) + 1e-6f);
    float4* orow = out + (size_t)row * (HDIM / 4);
#pragma unroll
    for (int it = 0; it < 8; ++it) {
        float2 f0 = __half22float2(*reinterpret_cast<__half2*>(&u[it].x));
        float2 f1 = __half22float2(*reinterpret_cast<__half2*>(&u[it].y));
        float4 w = nw[it * 32 + lane];
        float4 o4 = make_float4(f0.x * scale * w.x, f0.y * scale * w.y,
                                f1.x * scale * w.z, f1.y * scale * w.w);
        orow[it * 32 + lane] = o4;
    }
}

// ---------------------------------------------------------------------------
// Launcher
// ---------------------------------------------------------------------------
extern "C" void kernel_launch(void* const* d_in, const int* in_sizes, int n_in,
                              void* d_out, int out_size) {
    const float* x  = (const float*)d_in[0];
    const float* cw = (const float*)d_in[1];
    const float* nw = (const float*)d_in[2];
    float* out = (float*)d_out;

    const int H  = in_sizes[2];              // 1024
    const int M  = in_sizes[0] / H;          // 16384
    const int HH = H * H;
    const int L  = in_sizes[1] / HH;         // 20

    // 1) merged prep: reduce conv_w -> fp16 W  +  x -> fp16
    {
        int hh4 = HH / 4;
        int n4  = (M * H) / 4;
        int nbW = (hh4 + 255) / 256;
        int nbX = (n4 + 255) / 256;
        prep_kernel<<<nbW + nbX, 256>>>((const float4*)x, (const float4*)cw,
                                        L, hh4, n4, nbW, 1.0f / (float)L);
    }
    // 2) GEMM
    {
        cudaFuncSetAttribute(gemm_kernel,
                             cudaFuncAttributeMaxDynamicSharedMemorySize,
                             GEMM_SMEM_BYTES);
        dim3 grid(H / GBN, M / GBM);
        gemm_kernel<<<grid, 256, GEMM_SMEM_BYTES>>>();
    }
    // 3) RMSNorm (one warp per row, 8 rows per block)
    {
        rmsnorm_kernel<<<M / 8, 256>>>((const float4*)nw, (float4*)out);
    }
}